// round 17
// baseline (speedup 1.0000x reference)
#include <cuda_runtime.h>
#include <cuda_bf16.h>

#define SEQ   8192
#define DIN   256
#define H     2048
#define H4    8192
#define DOUT  64
#define NCTA  148
#define NTHR  448   // 14 warps
#define OUT_BASE (SEQ * DOUT)   // 524288

// ---------------- device scratch (allowed: __device__ globals) --------------
__device__ __nv_bfloat16 g_Whh[(size_t)H4 * H]; // 33.5 MB bf16 W_hh
__device__ float   g_xg [(size_t)SEQ * H4];     // 256 MB  x @ W_ih^T + b
__device__ float   g_hs [(size_t)SEQ * H];      // 64 MB   h history
__device__ float   g_hbuf[2][H];                // double-buffered h
__device__ float   g_WfcT[H * DOUT];            // W_fc transposed [k][d]
__device__ unsigned g_cbar[16 * 32];            // 16 chunk counters, 128B stride

// ---------------- prep: bf16 convert, transpose, init ----------------------
__global__ void prep_kernel(const float* __restrict__ Whh,
                            const float* __restrict__ hprev,
                            const float* __restrict__ Wfc)
{
    size_t stride = (size_t)gridDim.x * blockDim.x;
    size_t i0 = (size_t)blockIdx.x * blockDim.x + threadIdx.x;
    const size_t npair = (size_t)H4 * H / 2;
    for (size_t p = i0; p < npair; p += stride) {
        float2 v = ((const float2*)Whh)[p];
        ((__nv_bfloat162*)g_Whh)[p] = __floats2bfloat162_rn(v.x, v.y);
    }
    for (size_t i = i0; i < H; i += stride)
        g_hbuf[0][i] = hprev[i];
    for (size_t i = i0; i < (size_t)H * DOUT; i += stride) {
        int d = (int)(i & (DOUT - 1));
        int k = (int)(i >> 6);
        g_WfcT[i] = Wfc[(size_t)d * H + k];
    }
    if (i0 < 16 * 32) g_cbar[i0] = 0u;
}

// ---------------- xg GEMM: xg[t][r] = sum_k x[t][k] W_ih[r][k] + b ----------
__global__ void xg_kernel(const float* __restrict__ x,
                          const float* __restrict__ Wih,
                          const float* __restrict__ bih,
                          const float* __restrict__ bhh)
{
    __shared__ float As[64][68];
    __shared__ float Bs[64][68];
    const int tid = threadIdx.x;
    const int tx = tid & 15, ty = tid >> 4;
    const int t0 = blockIdx.y * 64, r0 = blockIdx.x * 64;

    float acc[4][4];
#pragma unroll
    for (int a = 0; a < 4; a++)
#pragma unroll
        for (int b = 0; b < 4; b++) acc[a][b] = 0.f;

    const int m  = tid >> 2;
    const int kb = (tid & 3) << 4;

    for (int k0 = 0; k0 < DIN; k0 += 64) {
#pragma unroll
        for (int q = 0; q < 4; q++) {
            float4 va = *(const float4*)(x   + (size_t)(t0 + m) * DIN + k0 + kb + q * 4);
            As[kb + q*4 + 0][m] = va.x; As[kb + q*4 + 1][m] = va.y;
            As[kb + q*4 + 2][m] = va.z; As[kb + q*4 + 3][m] = va.w;
            float4 vb = *(const float4*)(Wih + (size_t)(r0 + m) * DIN + k0 + kb + q * 4);
            Bs[kb + q*4 + 0][m] = vb.x; Bs[kb + q*4 + 1][m] = vb.y;
            Bs[kb + q*4 + 2][m] = vb.z; Bs[kb + q*4 + 3][m] = vb.w;
        }
        __syncthreads();
#pragma unroll
        for (int kk = 0; kk < 64; kk++) {
            float4 a4 = *(const float4*)&As[kk][ty * 4];
            float4 b4 = *(const float4*)&Bs[kk][tx * 4];
            acc[0][0] = fmaf(a4.x, b4.x, acc[0][0]);
            acc[0][1] = fmaf(a4.x, b4.y, acc[0][1]);
            acc[0][2] = fmaf(a4.x, b4.z, acc[0][2]);
            acc[0][3] = fmaf(a4.x, b4.w, acc[0][3]);
            acc[1][0] = fmaf(a4.y, b4.x, acc[1][0]);
            acc[1][1] = fmaf(a4.y, b4.y, acc[1][1]);
            acc[1][2] = fmaf(a4.y, b4.z, acc[1][2]);
            acc[1][3] = fmaf(a4.y, b4.w, acc[1][3]);
            acc[2][0] = fmaf(a4.z, b4.x, acc[2][0]);
            acc[2][1] = fmaf(a4.z, b4.y, acc[2][1]);
            acc[2][2] = fmaf(a4.z, b4.z, acc[2][2]);
            acc[2][3] = fmaf(a4.z, b4.w, acc[2][3]);
            acc[3][0] = fmaf(a4.w, b4.x, acc[3][0]);
            acc[3][1] = fmaf(a4.w, b4.y, acc[3][1]);
            acc[3][2] = fmaf(a4.w, b4.z, acc[3][2]);
            acc[3][3] = fmaf(a4.w, b4.w, acc[3][3]);
        }
        __syncthreads();
    }

    const int r = r0 + tx * 4;
    float b0 = bih[r + 0] + bhh[r + 0];
    float b1 = bih[r + 1] + bhh[r + 1];
    float b2 = bih[r + 2] + bhh[r + 2];
    float b3 = bih[r + 3] + bhh[r + 3];
#pragma unroll
    for (int mi = 0; mi < 4; mi++) {
        float4 o;
        o.x = acc[mi][0] + b0; o.y = acc[mi][1] + b1;
        o.z = acc[mi][2] + b2; o.w = acc[mi][3] + b3;
        *(float4*)(g_xg + (size_t)(t0 + ty * 4 + mi) * H4 + r) = o;
    }
}

// ---------------- persistent LSTM recurrence --------------------------------
__device__ __forceinline__ float sigm(float v) {
    return 1.f / (1.f + __expf(-v));
}
__device__ __forceinline__ float tanh_fast(float v) {
    return fmaf(2.f, sigm(2.f * v), -1.f);
}

// bf16 pair (packed in u32: elem k low, elem k+1 high) expanded via cheap ALU
#define BF_LO(u) __uint_as_float((u) << 16)
#define BF_HI(u) __uint_as_float((u) & 0xffff0000u)

// accumulate 4 weights (uint2 = 4 bf16) * 4 h values (float4)
#define ACC4(A, W, HV) do {                         \
    A = fmaf(BF_LO((W).x), (HV).x, A);              \
    A = fmaf(BF_HI((W).x), (HV).y, A);              \
    A = fmaf(BF_LO((W).y), (HV).z, A);              \
    A = fmaf(BF_HI((W).y), (HV).w, A);              \
} while (0)

// process one 128-wide k-chunk: 4 gate rows x (4 k per lane)
#define CHUNK(II, HV) do {                          \
    const uint2* _wc = wp + (II) * 128;             \
    uint2 _q0 = _wc[0];                             \
    uint2 _q1 = _wc[32];                            \
    uint2 _q2 = _wc[64];                            \
    uint2 _q3 = _wc[96];                            \
    ACC4(a0, _q0, HV);                              \
    ACC4(a1, _q1, HV);                              \
    ACC4(a2, _q2, HV);                              \
    ACC4(a3, _q3, HV);                              \
} while (0)

__global__ void __launch_bounds__(NTHR, 1)
lstm_kernel(const float* __restrict__ cprev, float* __restrict__ dout)
{
    // SMEM: ALL weights as uint2, layout ((w*16 + i)*4 + gate)*32 + l
    extern __shared__ uint2 sw[];   // 14*2048 uint2 = 229376 B

    const int cta = blockIdx.x;
    int jbase, nj;
    if (cta < 124) { nj = 14; jbase = cta * 14; }
    else           { nj = 13; jbase = 1736 + (cta - 124) * 13; }

    const int w = threadIdx.x >> 5;
    const int l = threadIdx.x & 31;
    const bool active = (w < nj);
    const int j = jbase + w;

    // ---- stage weights into SMEM
    const int tot = nj * 2048;   // uint2 per CTA
    for (int idx = threadIdx.x; idx < tot; idx += NTHR) {
        int l2   = idx & 31;
        int gate = (idx >> 5) & 3;
        int i    = (idx >> 7) & 15;
        int ww   = idx >> 11;
        int rowg = gate * H + jbase + ww;
        sw[idx] = ((const uint2*)g_Whh)[(size_t)rowg * 512 + i * 32 + l2];
    }
    __syncthreads();               // last block-wide sync in the kernel

    if (!active) return;           // 13-warp CTAs: warp 13 exits

    float c = 0.f, hkeep = 0.f;
    if (l == 0) c = cprev[j];

    const uint2* wp = sw + (size_t)w * 2048 + l;
    const int mychunk = j >> 7;                    // counter this warp arrives at
    unsigned* myflag = g_cbar + mychunk * 32;

    for (int t = 0; t < SEQ; t++) {
        const float* hb = g_hbuf[t & 1];
        const unsigned tgt = (unsigned)t * 128u;

        // prefetch xg (independent of h readiness)
        float xgv = 0.f;
        if (l < 4)
            xgv = __ldg(&g_xg[(size_t)t * H4 + l * H + j]);

        float a0 = 0.f, a1 = 0.f, a2 = 0.f, a3 = 0.f;

        // ---- survey all 16 chunk flags (lanes 0-15)
        unsigned v = 0;
        if (l < 16)
            asm volatile("ld.acquire.gpu.global.u32 %0, [%1];"
                         : "=r"(v) : "l"(g_cbar + l * 32) : "memory");
        unsigned okm = __ballot_sync(0xffffffffu, (l < 16) && (v >= tgt)) & 0xffffu;
        unsigned pend = 0xffffu & ~okm;

        if (okm == 0xffffu) {
            // fast path: everything ready — fully unrolled, ptxas batches loads
#pragma unroll
            for (int i = 0; i < 16; i++) {
                float4 hv = __ldcg((const float4*)(hb + i * 128 + l * 4));
                CHUNK(i, hv);
            }
        } else {
            // process ready set with depth-2 prefetch
            unsigned m = okm;
            int ia = -1, ib = -1;
            float4 hva, hvb;
            if (m) { ia = __ffs(m) - 1; m &= m - 1;
                     hva = __ldcg((const float4*)(hb + ia * 128 + l * 4)); }
            if (m) { ib = __ffs(m) - 1; m &= m - 1;
                     hvb = __ldcg((const float4*)(hb + ib * 128 + l * 4)); }
            while (ia >= 0) {
                CHUNK(ia, hva);
                ia = ib; hva = hvb;
                if (m) { ib = __ffs(m) - 1; m &= m - 1;
                         hvb = __ldcg((const float4*)(hb + ib * 128 + l * 4)); }
                else ib = -1;
            }
            // re-poll pending chunks; compute as they become ready
            while (pend) {
                unsigned vv = 0;
                bool mine = (l < 16) && ((pend >> l) & 1u);
                if (mine)
                    asm volatile("ld.acquire.gpu.global.u32 %0, [%1];"
                                 : "=r"(vv) : "l"(g_cbar + l * 32) : "memory");
                unsigned got = __ballot_sync(0xffffffffu, mine && (vv >= tgt));
                unsigned mm = got;
                while (mm) {
                    int i = __ffs(mm) - 1; mm &= mm - 1;
                    float4 hv = __ldcg((const float4*)(hb + i * 128 + l * 4));
                    CHUNK(i, hv);
                }
                pend &= ~got;
            }
        }

        // fold xg before reduction: lane g owns gate g
        a0 += (l == 0) ? xgv : 0.f;
        a1 += (l == 1) ? xgv : 0.f;
        a2 += (l == 2) ? xgv : 0.f;
        a3 += (l == 3) ? xgv : 0.f;
#pragma unroll
        for (int off = 16; off > 0; off >>= 1) {
            a0 += __shfl_down_sync(0xffffffffu, a0, off);
            a1 += __shfl_down_sync(0xffffffffu, a1, off);
            a2 += __shfl_down_sync(0xffffffffu, a2, off);
            a3 += __shfl_down_sync(0xffffffffu, a3, off);
        }
        if (l == 0) {
            float ig = sigm(a0);
            float fg = sigm(a1);
            float gg = tanh_fast(a2);
            float og = sigm(a3);
            c = fg * c + ig * gg;
            float hn = og * tanh_fast(c);
            hkeep = hn;
            g_hbuf[(t + 1) & 1][j] = hn;          // ordered before the release-add
            g_hs[(size_t)t * H + j] = hn;
            // per-warp arrival: release orders this thread's prior h store
            asm volatile("red.release.gpu.global.add.u32 [%0], %1;"
                         :: "l"(myflag), "r"(1u) : "memory");
        }
        __syncwarp();
    }

    if (l == 0) {
        dout[OUT_BASE + j]     = hkeep;   // hT
        dout[OUT_BASE + H + j] = c;       // cT
    }
}

// ---------------- output FC: out = sigmoid(hs @ W_fc^T + b_fc) --------------
__global__ void fc_kernel(const float* __restrict__ bfc, float* __restrict__ out)
{
    const int gw = (blockIdx.x * blockDim.x + threadIdx.x) >> 5;  // 0..4095
    const int l  = threadIdx.x & 31;
    const int t0 = gw * 2;

    float ax0 = 0.f, ay0 = 0.f, ax1 = 0.f, ay1 = 0.f;
    const float* hs0 = g_hs + (size_t)t0 * H;

#pragma unroll 8
    for (int k = 0; k < H; k++) {
        float2 wv = *(const float2*)(g_WfcT + k * DOUT + 2 * l);
        float h0 = __ldg(hs0 + k);
        float h1 = __ldg(hs0 + H + k);
        ax0 = fmaf(h0, wv.x, ax0); ay0 = fmaf(h0, wv.y, ay0);
        ax1 = fmaf(h1, wv.x, ax1); ay1 = fmaf(h1, wv.y, ay1);
    }
    const float bx = bfc[2 * l], by = bfc[2 * l + 1];
    float2 o;
    o.x = sigm(ax0 + bx); o.y = sigm(ay0 + by);
    *(float2*)(out + (size_t)(t0 + 0) * DOUT + 2 * l) = o;
    o.x = sigm(ax1 + bx); o.y = sigm(ay1 + by);
    *(float2*)(out + (size_t)(t0 + 1) * DOUT + 2 * l) = o;
}

// ---------------- launch -----------------------------------------------------
extern "C" void kernel_launch(void* const* d_in, const int* in_sizes, int n_in,
                              void* d_out, int out_size)
{
    const float* x     = (const float*)d_in[0];
    const float* hprev = (const float*)d_in[1];
    const float* cprev = (const float*)d_in[2];
    const float* Wih   = (const float*)d_in[3];
    const float* Whh   = (const float*)d_in[4];
    const float* bih   = (const float*)d_in[5];
    const float* bhh   = (const float*)d_in[6];
    const float* Wfc   = (const float*)d_in[7];
    const float* bfc   = (const float*)d_in[8];
    float* out = (float*)d_out;

    const int smem_bytes = 14 * 2048 * 8;   // 229376 B
    cudaFuncSetAttribute(lstm_kernel,
                         cudaFuncAttributeMaxDynamicSharedMemorySize, smem_bytes);

    prep_kernel<<<4096, 256>>>(Whh, hprev, Wfc);

    dim3 gg(H4 / 64, SEQ / 64);
    xg_kernel<<<gg, 256>>>(x, Wih, bih, bhh);

    lstm_kernel<<<NCTA, NTHR, smem_bytes>>>(cprev, out);

    fc_kernel<<<512, 256>>>(bfc, out);
}